// round 14
// baseline (speedup 1.0000x reference)
#include <cuda_runtime.h>
#include <cuda_fp16.h>
#include <math.h>
#include <stdint.h>

#define B 128
#define T 2048
#define H 200
#define G4 800
#define NSTEP 5
#define ENC_N (B * T * H)   // 52,428,800

// ---- scratch ----
__device__ float g_qproj[B * H];
__device__ float g_gbase[B * G4];
__device__ float g_scores[B * T];
__device__ float g_ctxpart[4][B * H];   // per-T-quarter context partials
__device__ __half g_ench[ENC_N];        // fp16 enc copy (written by k_scores)
__device__ __half g_uah[H * H];         // fp16 Ua copy (written by k_pre)

__device__ __forceinline__ float tanh_fast(float x) {
    float e = __expf(2.0f * x);
    return 1.0f - __fdividef(2.0f, e + 1.0f);
}
__device__ __forceinline__ float sig_fast(float x) {
    return __fdividef(1.0f, 1.0f + __expf(-x));
}
__device__ __forceinline__ uint32_t smem_u32(const void* p) {
    uint32_t a;
    asm("{ .reg .u64 t; cvta.to.shared.u64 t, %1; cvt.u32.u64 %0, t; }" : "=r"(a) : "l"(p));
    return a;
}
__device__ __forceinline__ void cp_async16(uint32_t dst, const void* src, uint32_t src_sz) {
    asm volatile("cp.async.cg.shared.global [%0], [%1], 16, %2;"
                 :: "r"(dst), "l"(src), "r"(src_sz) : "memory");
}
__device__ __forceinline__ void mma_f16(float* d, const uint32_t* a, const uint32_t* b) {
    asm volatile("mma.sync.aligned.m16n8k16.row.col.f32.f16.f16.f32 "
                 "{%0,%1,%2,%3}, {%4,%5,%6,%7}, {%8,%9}, {%0,%1,%2,%3};"
                 : "+f"(d[0]), "+f"(d[1]), "+f"(d[2]), "+f"(d[3])
                 : "r"(a[0]), "r"(a[1]), "r"(a[2]), "r"(a[3]), "r"(b[0]), "r"(b[1]));
}
__device__ __forceinline__ uint4 cvt8(const float4& a, const float4& b) {
    uint4 o;
    *reinterpret_cast<__half2*>(&o.x) = __floats2half2_rn(a.x, a.y);
    *reinterpret_cast<__half2*>(&o.y) = __floats2half2_rn(a.z, a.w);
    *reinterpret_cast<__half2*>(&o.z) = __floats2half2_rn(b.x, b.y);
    *reinterpret_cast<__half2*>(&o.w) = __floats2half2_rn(b.z, b.w);
    return o;
}

// ============================================================
// Kernel 1: blocks 0..127: qproj = h0 @ Wa.T + ba;
//           blocks 128..132: convert Ua -> fp16 g_uah.
// ============================================================
#define N8U (H * H / 8)   // 5000 groups of 8 floats

__global__ void k_pre(const float* __restrict__ h0, const float* __restrict__ Wa,
                      const float* __restrict__ ba, const float* __restrict__ Ua) {
    if (blockIdx.x >= B) {
        const int base = (blockIdx.x - B) * 256 + threadIdx.x;
        for (int j = base; j < N8U; j += 5 * 256) {
            const float4* s4 = (const float4*)Ua;
            float4 v0 = s4[2 * j], v1 = s4[2 * j + 1];
            ((uint4*)g_uah)[j] = cvt8(v0, v1);
        }
        return;
    }
    __shared__ float q[H];
    const int b = blockIdx.x;
    for (int k = threadIdx.x; k < H; k += blockDim.x) q[k] = h0[b * H + k];
    __syncthreads();
    for (int j = threadIdx.x; j < H; j += blockDim.x) {
        const float* w = Wa + j * H;
        float a0 = 0.f, a1 = 0.f;
        #pragma unroll 4
        for (int k = 0; k < H; k += 2) { a0 += w[k] * q[k]; a1 += w[k + 1] * q[k + 1]; }
        g_qproj[b * H + j] = a0 + a1 + ba[j];
    }
}

// ============================================================
// Kernel 2: score GEMM + enc fp16 conversion fused.
// A (enc) read as fp32, converted in-register (prefetch one chunk ahead),
// STS fp16 to smem + STG fp16 to g_ench. B (Ua fp16) via cp.async ring.
// Block tile 64 t x 224 n (full N), grid (T/64, B).
// ============================================================
#define TMR 64
#define NBF 224
#define NKCH 7
#define SSTR 20
#define ROWS_ST (TMR + NBF)   // 288

__global__ __launch_bounds__(256)
void k_scores_mma(const float* __restrict__ enc,
                  const float* __restrict__ bua, const float* __restrict__ Va) {
    __shared__ __align__(16) uint32_t sS[2][ROWS_ST * SSTR];  // 46.08 KB
    __shared__ float sQ[NBF];
    __shared__ float sV[NBF];
    __shared__ float sRow[TMR];

    const int tid  = threadIdx.x;
    const int wid  = tid >> 5, lane = tid & 31;
    const int b    = blockIdx.y;
    const int t0   = blockIdx.x * TMR;

    const int mw = wid & 1;
    const int nw = wid >> 1;
    const int rowbase = mw * 32;
    const int nbase   = nw * 56;
    const int q = lane >> 2;
    const int c = lane & 3;

    for (int i = tid; i < NBF; i += 256) {
        sQ[i] = (i < H) ? g_qproj[b * H + i] + bua[i] : 0.f;
        sV[i] = (i < H) ? Va[i] : 0.f;
    }
    if (tid < TMR) sRow[tid] = 0.f;

    float acc[2][7][4];
    #pragma unroll
    for (int mt = 0; mt < 2; ++mt)
        #pragma unroll
        for (int nt = 0; nt < 7; ++nt)
            #pragma unroll
            for (int j = 0; j < 4; ++j) acc[mt][nt][j] = 0.f;

    const float*  encB32 = enc    + ((long)b * T + t0) * H;
    __half*       enchB  = g_ench + ((long)b * T + t0) * H;
    const uint32_t base0 = smem_u32(&sS[0][0]);

    const int arow = tid >> 2;        // 0..63
    const int ag   = tid & 3;         // 0..3

    // ---- A chunk load (fp32 registers) ----
    auto ldA = [&](int kc, float4& x0, float4& x1, bool& ok) {
        const int gk = kc * 32 + ag * 8;
        ok = (gk + 8 <= H);
        if (ok) {
            x0 = *(const float4*)(encB32 + (long)arow * H + gk);
            x1 = *(const float4*)(encB32 + (long)arow * H + gk + 4);
        } else {
            x0 = make_float4(0.f, 0.f, 0.f, 0.f);
            x1 = x0;
        }
    };
    // ---- B fill via cp.async ----
    auto fillB = [&](int kc, int st) {
        const int k0 = kc * 32;
        const uint32_t stOff = base0 + (uint32_t)st * ROWS_ST * SSTR * 4;
        for (int i = tid; i < NBF * 4; i += 256) {
            const int row = i >> 2, g = i & 3;
            const int gk = k0 + g * 8;
            const bool ok = (row < H) && (gk + 8 <= H);
            const void* src = ok ? (const void*)(g_uah + (long)row * H + gk) : (const void*)g_uah;
            cp_async16(stOff + (uint32_t)(((TMR + row) * SSTR + g * 4) * 4), src, ok ? 16u : 0u);
        }
        asm volatile("cp.async.commit_group;" ::: "memory");
    };

    float4 a0, a1, n0, n1;
    bool okA, okN;
    ldA(0, a0, a1, okA);
    fillB(0, 0);

    for (int kc = 0; kc < NKCH; ++kc) {
        const int st = kc & 1;
        // convert + STS this chunk's A; STG fp16 tile to g_ench
        {
            const uint4 v = okA ? cvt8(a0, a1) : make_uint4(0u, 0u, 0u, 0u);
            uint32_t* dst = &sS[st][arow * SSTR + ag * 4];
            *reinterpret_cast<uint4*>(dst) = v;
            if (okA) {
                const int gk = kc * 32 + ag * 8;
                *reinterpret_cast<uint4*>(enchB + (long)arow * H + gk) = v;
            }
        }
        if (kc + 1 < NKCH) {
            fillB(kc + 1, st ^ 1);
            ldA(kc + 1, n0, n1, okN);       // LDG latency hides under compute below
            asm volatile("cp.async.wait_group 1;" ::: "memory");
        } else {
            asm volatile("cp.async.wait_group 0;" ::: "memory");
        }
        __syncthreads();

        const uint32_t (*W)[SSTR] = (const uint32_t (*)[SSTR])&sS[st][0];
        #pragma unroll
        for (int ks = 0; ks < 2; ++ks) {
            const int wk = ks * 8;
            uint32_t afr[2][4];
            #pragma unroll
            for (int mt = 0; mt < 2; ++mt) {
                const int R = rowbase + mt * 16 + q;
                afr[mt][0] = W[R][wk + c];
                afr[mt][1] = W[R + 8][wk + c];
                afr[mt][2] = W[R][wk + c + 4];
                afr[mt][3] = W[R + 8][wk + c + 4];
            }
            uint32_t bfr[7][2];
            #pragma unroll
            for (int nt = 0; nt < 7; ++nt) {
                const int N = TMR + nbase + nt * 8 + q;
                bfr[nt][0] = W[N][wk + c];
                bfr[nt][1] = W[N][wk + c + 4];
            }
            #pragma unroll
            for (int mt = 0; mt < 2; ++mt)
                #pragma unroll
                for (int nt = 0; nt < 7; ++nt)
                    mma_f16(acc[mt][nt], afr[mt], bfr[nt]);
        }
        __syncthreads();
        a0 = n0; a1 = n1; okA = okN;
    }

    // ---- epilogue: tanh + Va reduce ----
    float pLo[2], pHi[2];
    #pragma unroll
    for (int mt = 0; mt < 2; ++mt) { pLo[mt] = 0.f; pHi[mt] = 0.f; }
    #pragma unroll
    for (int nt = 0; nt < 7; ++nt) {
        const int col0 = nbase + nt * 8 + c * 2;
        const float v0 = sV[col0],     q0 = sQ[col0];
        const float v1 = sV[col0 + 1], q1 = sQ[col0 + 1];
        #pragma unroll
        for (int mt = 0; mt < 2; ++mt) {
            pLo[mt] += v0 * tanh_fast(q0 + acc[mt][nt][0]) + v1 * tanh_fast(q1 + acc[mt][nt][1]);
            pHi[mt] += v0 * tanh_fast(q0 + acc[mt][nt][2]) + v1 * tanh_fast(q1 + acc[mt][nt][3]);
        }
    }
    #pragma unroll
    for (int mt = 0; mt < 2; ++mt) {
        #pragma unroll
        for (int o = 1; o <= 2; o <<= 1) {
            pLo[mt] += __shfl_xor_sync(0xffffffffu, pLo[mt], o);
            pHi[mt] += __shfl_xor_sync(0xffffffffu, pHi[mt], o);
        }
        if (c == 0) {
            const int R = rowbase + mt * 16 + q;
            atomicAdd(&sRow[R], pLo[mt]);
            atomicAdd(&sRow[R + 8], pHi[mt]);
        }
    }
    __syncthreads();
    if (tid < TMR) g_scores[b * T + t0 + tid] = sRow[tid];
}

// ============================================================
// Kernel 3: softmax + context, fp16 enc, 4-way T-split (grid (B, 4)).
// ============================================================
#define CTXTH 800
#define HP 100
#define NSL 8
#define TQ (T / 4)            // 512
#define TSL (TQ / NSL)        // 64

__global__ void k_ctx() {
    __shared__ float sW[T];
    __shared__ float sPx[NSL][HP];
    __shared__ float sPy[NSL][HP];
    __shared__ float red[32];
    const int b = blockIdx.x, quar = blockIdx.y, tid = threadIdx.x;
    const int lane = tid & 31, wid = tid >> 5;

    float m = -1e30f;
    for (int t = tid; t < T; t += CTXTH) { float s = g_scores[b * T + t]; sW[t] = s; m = fmaxf(m, s); }
    #pragma unroll
    for (int o = 16; o; o >>= 1) m = fmaxf(m, __shfl_xor_sync(0xffffffffu, m, o));
    if (lane == 0) red[wid] = m;
    __syncthreads();
    if (tid < 32) {
        float w = (tid < CTXTH / 32) ? red[tid] : -1e30f;
        #pragma unroll
        for (int o = 16; o; o >>= 1) w = fmaxf(w, __shfl_xor_sync(0xffffffffu, w, o));
        if (tid == 0) red[0] = w;
    }
    __syncthreads();
    m = red[0];
    __syncthreads();

    float sum = 0.f;
    for (int t = tid; t < T; t += CTXTH) { float e = __expf(sW[t] - m); sW[t] = e; sum += e; }
    #pragma unroll
    for (int o = 16; o; o >>= 1) sum += __shfl_xor_sync(0xffffffffu, sum, o);
    if (lane == 0) red[wid] = sum;
    __syncthreads();
    if (tid < 32) {
        float w = (tid < CTXTH / 32) ? red[tid] : 0.f;
        #pragma unroll
        for (int o = 16; o; o >>= 1) w += __shfl_xor_sync(0xffffffffu, w, o);
        if (tid == 0) red[0] = w;
    }
    __syncthreads();
    const float inv = __fdividef(1.0f, red[0]);

    const int sl = tid / HP;
    const int p  = tid - sl * HP;
    const __half2* eB = (const __half2*)g_ench + (long)b * T * HP + p;
    float ax[4], ay[4];
    #pragma unroll
    for (int j = 0; j < 4; ++j) { ax[j] = 0.f; ay[j] = 0.f; }
    const int tbeg = quar * TQ + sl * TSL, tend = tbeg + TSL;
    for (int t = tbeg; t < tend; t += 4) {
        #pragma unroll
        for (int j = 0; j < 4; ++j) {
            const float2 v = __half22float2(eB[(long)(t + j) * HP]);
            const float w = sW[t + j];
            ax[j] += w * v.x;
            ay[j] += w * v.y;
        }
    }
    sPx[sl][p] = (ax[0] + ax[1]) + (ax[2] + ax[3]);
    sPy[sl][p] = (ay[0] + ay[1]) + (ay[2] + ay[3]);
    __syncthreads();
    if (tid < H) {
        const int pp = tid >> 1;
        float acc = 0.f;
        if (tid & 1) {
            #pragma unroll
            for (int s = 0; s < NSL; ++s) acc += sPy[s][pp];
        } else {
            #pragma unroll
            for (int s = 0; s < NSL; ++s) acc += sPx[s][pp];
        }
        g_ctxpart[quar][b * H + tid] = acc * inv;
    }
}

// ============================================================
// Kernel 3.5: gate base GEMM (sums the four context partials)
// ============================================================
__global__ void k_gates(const float* __restrict__ h0, const float* __restrict__ Wih,
                        const float* __restrict__ Whh, const float* __restrict__ bih,
                        const float* __restrict__ bhh) {
    __shared__ float sC[8][200];
    __shared__ float sQT[8][200];
    __shared__ float sW[100][51];
    const int tid  = threadIdx.x;
    const int gl   = tid % 100;
    const int bb   = tid / 100;
    const int gBase = blockIdx.x * 100;
    const int b0   = blockIdx.y * 8;
    const int g    = gBase + gl;

    for (int i = tid; i < 8 * 200; i += 800) {
        const int r = i / 200, k = i % 200;
        const int idx = (b0 + r) * H + k;
        sC[r][k]  = (g_ctxpart[0][idx] + g_ctxpart[1][idx])
                  + (g_ctxpart[2][idx] + g_ctxpart[3][idx]);
        sQT[r][k] = h0[idx];
    }

    float acc = bih[g] + bhh[g];
    const float* myC = sC[bb];
    const float* myQ = sQT[bb];

    #pragma unroll
    for (int mat = 0; mat < 2; ++mat) {
        #pragma unroll
        for (int ch = 0; ch < 4; ++ch) {
            __syncthreads();
            for (int i = tid; i < 100 * 50; i += 800) {
                const int r = i / 50, cc = i % 50;
                const int gg = gBase + r;
                sW[r][cc] = (mat == 0) ? Wih[gg * (H + 1) + 1 + ch * 50 + cc]
                                       : Whh[gg * H + ch * 50 + cc];
            }
            __syncthreads();
            const float* src = ((mat == 0) ? myC : myQ) + ch * 50;
            float a0 = 0.f, a1 = 0.f;
            #pragma unroll 5
            for (int k = 0; k < 50; k += 2) { a0 += sW[gl][k] * src[k]; a1 += sW[gl][k + 1] * src[k + 1]; }
            acc += a0 + a1;
        }
    }
    g_gbase[(b0 + bb) * G4 + g] = acc;
}

// ============================================================
// Kernel 4: decoder (unchanged)
// ============================================================
__global__ void k_dec(const float* __restrict__ x, const float* __restrict__ c0in,
                      const float* __restrict__ Wih,
                      const float* __restrict__ W1, const float* __restrict__ b1,
                      const float* __restrict__ W2, const float* __restrict__ b2,
                      const float* __restrict__ W3, const float* __restrict__ b3,
                      float* __restrict__ out) {
    __shared__ float sGB[G4];
    __shared__ float sWx[G4];
    __shared__ float sR[H];
    __shared__ float sO1[100];
    __shared__ float sO2[52];
    __shared__ float sRed[64];
    __shared__ float sY;
    __shared__ float sW2[5000];
    __shared__ float sW3[52];
    __shared__ float sB1[100];
    __shared__ float sB2c[52];

    const int b = blockIdx.x, tid = threadIdx.x;
    const int lane = tid & 31;
    const unsigned m8  = 0xFFu   << (lane & 24);
    const unsigned m16 = 0xFFFFu << (lane & 16);

    for (int i = tid; i < 5000; i += G4) sW2[i] = W2[i];
    if (tid < 50)  sW3[tid] = W3[tid];
    if (tid < 100) sB1[tid] = b1[tid];
    if (tid < 50)  sB2c[tid] = b2[tid];
    sGB[tid] = g_gbase[b * G4 + tid];
    sWx[tid] = Wih[tid * (H + 1)];

    const int j8 = tid >> 3, q8 = tid & 7;
    float w1r[25];
    {
        const float* w1p = W1 + j8 * H + q8 * 25;
        #pragma unroll
        for (int k = 0; k < 25; ++k) w1r[k] = w1p[k];
    }
    const float cprev = (tid < H) ? c0in[b * H + tid] : 0.f;
    __syncthreads();

    float xt = x[b];
    const int j16 = tid >> 4, q16 = tid & 15;
    for (int s = 0; s < NSTEP; ++s) {
        if (tid < H) {
            const float gi = sGB[tid]         + xt * sWx[tid];
            const float gf = sGB[H + tid]     + xt * sWx[H + tid];
            const float gg = sGB[2 * H + tid] + xt * sWx[2 * H + tid];
            const float go = sGB[3 * H + tid] + xt * sWx[3 * H + tid];
            const float c  = sig_fast(gf) * cprev + sig_fast(gi) * tanh_fast(gg);
            const float h  = sig_fast(go) * tanh_fast(c);
            sR[tid] = fmaxf(h, 0.f);
        }
        __syncthreads();
        {
            const float* r = sR + q8 * 25;
            float v = 0.f;
            #pragma unroll
            for (int k = 0; k < 25; ++k) v += w1r[k] * r[k];
            v += __shfl_xor_sync(m8, v, 1);
            v += __shfl_xor_sync(m8, v, 2);
            v += __shfl_xor_sync(m8, v, 4);
            if (q8 == 0) sO1[j8] = fmaxf(v + sB1[j8], 0.f);
        }
        __syncthreads();
        {
            const float* w = sW2 + j16 * 100;
            float v = 0.f;
            #pragma unroll
            for (int kk = 0; kk < 7; ++kk) {
                const int k = q16 * 7 + kk;
                if (k < 100) v += w[k] * sO1[k];
            }
            v += __shfl_xor_sync(m16, v, 1);
            v += __shfl_xor_sync(m16, v, 2);
            v += __shfl_xor_sync(m16, v, 4);
            v += __shfl_xor_sync(m16, v, 8);
            if (q16 == 0) sO2[j16] = fmaxf(v + sB2c[j16], 0.f);
        }
        __syncthreads();
        if (tid < 64) sRed[tid] = (tid < 50) ? sW3[tid] * sO2[tid] : 0.f;
        __syncthreads();
        if (tid < 32) {
            float v = sRed[tid] + sRed[tid + 32];
            #pragma unroll
            for (int o = 16; o; o >>= 1) v += __shfl_xor_sync(0xffffffffu, v, o);
            if (tid == 0) { float y = v + b3[0]; out[b * NSTEP + s] = y; sY = y; }
        }
        __syncthreads();
        xt = sY;
    }
}

// ============================================================
extern "C" void kernel_launch(void* const* d_in, const int* in_sizes, int n_in,
                              void* d_out, int out_size) {
    const float* x   = (const float*)d_in[0];
    const float* h0  = (const float*)d_in[1];
    const float* c0  = (const float*)d_in[2];
    const float* enc = (const float*)d_in[3];
    const float* Wa  = (const float*)d_in[4];
    const float* ba  = (const float*)d_in[5];
    const float* Ua  = (const float*)d_in[6];
    const float* bua = (const float*)d_in[7];
    const float* Va  = (const float*)d_in[8];
    // d_in[9] = bva (softmax-shift-invariant, unused)
    const float* Wih = (const float*)d_in[10];
    const float* Whh = (const float*)d_in[11];
    const float* bih = (const float*)d_in[12];
    const float* bhh = (const float*)d_in[13];
    const float* W1  = (const float*)d_in[14];
    const float* b1  = (const float*)d_in[15];
    const float* W2  = (const float*)d_in[16];
    const float* b2  = (const float*)d_in[17];
    const float* W3  = (const float*)d_in[18];
    const float* b3  = (const float*)d_in[19];
    float* out = (float*)d_out;

    k_pre<<<B + 5, 256>>>(h0, Wa, ba, Ua);
    k_scores_mma<<<dim3(T / TMR, B), 256>>>(enc, bua, Va);
    k_ctx<<<dim3(B, 4), CTXTH>>>();
    k_gates<<<dim3(8, 16), 800>>>(h0, Wih, Whh, bih, bhh);
    k_dec<<<B, G4>>>(x, c0, Wih, W1, b1, W2, b2, W3, b3, out);
}

// round 16
// speedup vs baseline: 1.0875x; 1.0875x over previous
#include <cuda_runtime.h>
#include <cuda_fp16.h>
#include <math.h>
#include <stdint.h>

#define B 128
#define T 2048
#define H 200
#define G4 800
#define NSTEP 5
#define ENC_N (B * T * H)   // 52,428,800

// ---- scratch ----
__device__ float g_qproj[B * H];
__device__ float g_gbase[B * G4];
__device__ float g_scores[B * T];
__device__ float g_ctxpart[4][B * H];   // per-T-quarter context partials
__device__ __half g_ench[ENC_N];        // fp16 copy of encoder_output (105 MB)
__device__ __half g_uah[H * H];         // fp16 copy of Ua

__device__ __forceinline__ float tanh_fast(float x) {
    float e = __expf(2.0f * x);
    return 1.0f - __fdividef(2.0f, e + 1.0f);
}
__device__ __forceinline__ float sig_fast(float x) {
    return __fdividef(1.0f, 1.0f + __expf(-x));
}
__device__ __forceinline__ uint32_t smem_u32(const void* p) {
    uint32_t a;
    asm("{ .reg .u64 t; cvta.to.shared.u64 t, %1; cvt.u32.u64 %0, t; }" : "=r"(a) : "l"(p));
    return a;
}
__device__ __forceinline__ void cp_async16(uint32_t dst, const void* src, uint32_t src_sz) {
    asm volatile("cp.async.cg.shared.global [%0], [%1], 16, %2;"
                 :: "r"(dst), "l"(src), "r"(src_sz) : "memory");
}
__device__ __forceinline__ void mma_f16(float* d, const uint32_t* a, const uint32_t* b) {
    asm volatile("mma.sync.aligned.m16n8k16.row.col.f32.f16.f16.f32 "
                 "{%0,%1,%2,%3}, {%4,%5,%6,%7}, {%8,%9}, {%0,%1,%2,%3};"
                 : "+f"(d[0]), "+f"(d[1]), "+f"(d[2]), "+f"(d[3])
                 : "r"(a[0]), "r"(a[1]), "r"(a[2]), "r"(a[3]), "r"(b[0]), "r"(b[1]));
}

// ============================================================
// Kernel 0: fp32 -> fp16 conversion, 8 floats/thread
// ============================================================
#define N8E (ENC_N / 8)
#define N8U (H * H / 8)

__global__ void k_cvt(const float* __restrict__ enc, const float* __restrict__ Ua) {
    const long i = (long)blockIdx.x * blockDim.x + threadIdx.x;
    const float4* s4;
    uint4* d4;
    long j;
    if (i < N8E)            { s4 = (const float4*)enc; d4 = (uint4*)g_ench; j = i; }
    else if (i - N8E < N8U) { s4 = (const float4*)Ua;  d4 = (uint4*)g_uah;  j = i - N8E; }
    else return;
    float4 v0 = s4[2 * j], v1 = s4[2 * j + 1];
    uint4 o;
    *reinterpret_cast<__half2*>(&o.x) = __floats2half2_rn(v0.x, v0.y);
    *reinterpret_cast<__half2*>(&o.y) = __floats2half2_rn(v0.z, v0.w);
    *reinterpret_cast<__half2*>(&o.z) = __floats2half2_rn(v1.x, v1.y);
    *reinterpret_cast<__half2*>(&o.w) = __floats2half2_rn(v1.z, v1.w);
    d4[j] = o;
}

// ============================================================
// Kernel 1: qproj = h0 @ Wa.T + ba
// ============================================================
__global__ void k_pre(const float* __restrict__ h0, const float* __restrict__ Wa,
                      const float* __restrict__ ba) {
    __shared__ float q[H];
    const int b = blockIdx.x;
    for (int k = threadIdx.x; k < H; k += blockDim.x) q[k] = h0[b * H + k];
    __syncthreads();
    for (int j = threadIdx.x; j < H; j += blockDim.x) {
        const float* w = Wa + j * H;
        float a0 = 0.f, a1 = 0.f;
        #pragma unroll 4
        for (int k = 0; k < H; k += 2) { a0 += w[k] * q[k]; a1 += w[k + 1] * q[k + 1]; }
        g_qproj[b * H + j] = a0 + a1 + ba[j];
    }
}

// ============================================================
// Kernel 2: score GEMM (proven R13 form): fp16 mma + cp.async
// double-buffer, T-split 64 t x 224 n (full N), enc read once (fp16).
// ============================================================
#define TMR 64
#define NBF 224
#define NKCH 7
#define SSTR 20
#define ROWS_ST (TMR + NBF)   // 288

__global__ __launch_bounds__(256)
void k_scores_mma(const float* __restrict__ bua, const float* __restrict__ Va) {
    __shared__ __align__(16) uint32_t sS[2][ROWS_ST * SSTR];  // 46.08 KB
    __shared__ float sQ[NBF];
    __shared__ float sV[NBF];
    __shared__ float sRow[TMR];

    const int tid  = threadIdx.x;
    const int wid  = tid >> 5, lane = tid & 31;
    const int b    = blockIdx.y;
    const int t0   = blockIdx.x * TMR;

    const int mw = wid & 1;
    const int nw = wid >> 1;
    const int rowbase = mw * 32;
    const int nbase   = nw * 56;
    const int q = lane >> 2;
    const int c = lane & 3;

    for (int i = tid; i < NBF; i += 256) {
        sQ[i] = (i < H) ? g_qproj[b * H + i] + bua[i] : 0.f;
        sV[i] = (i < H) ? Va[i] : 0.f;
    }
    if (tid < TMR) sRow[tid] = 0.f;

    float acc[2][7][4];
    #pragma unroll
    for (int mt = 0; mt < 2; ++mt)
        #pragma unroll
        for (int nt = 0; nt < 7; ++nt)
            #pragma unroll
            for (int j = 0; j < 4; ++j) acc[mt][nt][j] = 0.f;

    const __half* encB = g_ench + ((long)b * T + t0) * H;
    const uint32_t base0 = smem_u32(&sS[0][0]);

    auto fill = [&](int kc, int st) {
        const int k0 = kc * 32;
        const uint32_t stOff = base0 + (uint32_t)st * ROWS_ST * SSTR * 4;
        {
            const int row = tid >> 2, g = tid & 3;
            const int gk = k0 + g * 8;
            const bool ok = (gk + 8 <= H);
            const void* src = ok ? (const void*)(encB + (long)row * H + gk) : (const void*)encB;
            cp_async16(stOff + (uint32_t)((row * SSTR + g * 4) * 4), src, ok ? 16u : 0u);
        }
        for (int i = tid; i < NBF * 4; i += 256) {
            const int row = i >> 2, g = i & 3;
            const int gk = k0 + g * 8;
            const bool ok = (row < H) && (gk + 8 <= H);
            const void* src = ok ? (const void*)(g_uah + (long)row * H + gk) : (const void*)g_uah;
            cp_async16(stOff + (uint32_t)(((TMR + row) * SSTR + g * 4) * 4), src, ok ? 16u : 0u);
        }
        asm volatile("cp.async.commit_group;" ::: "memory");
    };

    fill(0, 0);

    for (int kc = 0; kc < NKCH; ++kc) {
        const int st = kc & 1;
        if (kc + 1 < NKCH) {
            fill(kc + 1, st ^ 1);
            asm volatile("cp.async.wait_group 1;" ::: "memory");
        } else {
            asm volatile("cp.async.wait_group 0;" ::: "memory");
        }
        __syncthreads();

        const uint32_t (*W)[SSTR] = (const uint32_t (*)[SSTR])&sS[st][0];
        #pragma unroll
        for (int ks = 0; ks < 2; ++ks) {
            const int wk = ks * 8;
            uint32_t afr[2][4];
            #pragma unroll
            for (int mt = 0; mt < 2; ++mt) {
                const int R = rowbase + mt * 16 + q;
                afr[mt][0] = W[R][wk + c];
                afr[mt][1] = W[R + 8][wk + c];
                afr[mt][2] = W[R][wk + c + 4];
                afr[mt][3] = W[R + 8][wk + c + 4];
            }
            uint32_t bfr[7][2];
            #pragma unroll
            for (int nt = 0; nt < 7; ++nt) {
                const int N = TMR + nbase + nt * 8 + q;
                bfr[nt][0] = W[N][wk + c];
                bfr[nt][1] = W[N][wk + c + 4];
            }
            #pragma unroll
            for (int mt = 0; mt < 2; ++mt)
                #pragma unroll
                for (int nt = 0; nt < 7; ++nt)
                    mma_f16(acc[mt][nt], afr[mt], bfr[nt]);
        }
        __syncthreads();
    }

    // ---- epilogue: tanh + Va reduce ----
    float pLo[2], pHi[2];
    #pragma unroll
    for (int mt = 0; mt < 2; ++mt) { pLo[mt] = 0.f; pHi[mt] = 0.f; }
    #pragma unroll
    for (int nt = 0; nt < 7; ++nt) {
        const int col0 = nbase + nt * 8 + c * 2;
        const float v0 = sV[col0],     q0 = sQ[col0];
        const float v1 = sV[col0 + 1], q1 = sQ[col0 + 1];
        #pragma unroll
        for (int mt = 0; mt < 2; ++mt) {
            pLo[mt] += v0 * tanh_fast(q0 + acc[mt][nt][0]) + v1 * tanh_fast(q1 + acc[mt][nt][1]);
            pHi[mt] += v0 * tanh_fast(q0 + acc[mt][nt][2]) + v1 * tanh_fast(q1 + acc[mt][nt][3]);
        }
    }
    #pragma unroll
    for (int mt = 0; mt < 2; ++mt) {
        #pragma unroll
        for (int o = 1; o <= 2; o <<= 1) {
            pLo[mt] += __shfl_xor_sync(0xffffffffu, pLo[mt], o);
            pHi[mt] += __shfl_xor_sync(0xffffffffu, pHi[mt], o);
        }
        if (c == 0) {
            const int R = rowbase + mt * 16 + q;
            atomicAdd(&sRow[R], pLo[mt]);
            atomicAdd(&sRow[R + 8], pHi[mt]);
        }
    }
    __syncthreads();
    if (tid < TMR) g_scores[b * T + t0 + tid] = sRow[tid];
}

// ============================================================
// Kernel 3: softmax + context, fp16 enc, 4-way T-split (grid (B, 4)).
// ============================================================
#define CTXTH 800
#define HP 100
#define NSL 8
#define TQ (T / 4)            // 512
#define TSL (TQ / NSL)        // 64

__global__ void k_ctx() {
    __shared__ float sW[T];
    __shared__ float sPx[NSL][HP];
    __shared__ float sPy[NSL][HP];
    __shared__ float red[32];
    const int b = blockIdx.x, quar = blockIdx.y, tid = threadIdx.x;
    const int lane = tid & 31, wid = tid >> 5;

    float m = -1e30f;
    for (int t = tid; t < T; t += CTXTH) { float s = g_scores[b * T + t]; sW[t] = s; m = fmaxf(m, s); }
    #pragma unroll
    for (int o = 16; o; o >>= 1) m = fmaxf(m, __shfl_xor_sync(0xffffffffu, m, o));
    if (lane == 0) red[wid] = m;
    __syncthreads();
    if (tid < 32) {
        float w = (tid < CTXTH / 32) ? red[tid] : -1e30f;
        #pragma unroll
        for (int o = 16; o; o >>= 1) w = fmaxf(w, __shfl_xor_sync(0xffffffffu, w, o));
        if (tid == 0) red[0] = w;
    }
    __syncthreads();
    m = red[0];
    __syncthreads();

    float sum = 0.f;
    for (int t = tid; t < T; t += CTXTH) { float e = __expf(sW[t] - m); sW[t] = e; sum += e; }
    #pragma unroll
    for (int o = 16; o; o >>= 1) sum += __shfl_xor_sync(0xffffffffu, sum, o);
    if (lane == 0) red[wid] = sum;
    __syncthreads();
    if (tid < 32) {
        float w = (tid < CTXTH / 32) ? red[tid] : 0.f;
        #pragma unroll
        for (int o = 16; o; o >>= 1) w += __shfl_xor_sync(0xffffffffu, w, o);
        if (tid == 0) red[0] = w;
    }
    __syncthreads();
    const float inv = __fdividef(1.0f, red[0]);

    const int sl = tid / HP;
    const int p  = tid - sl * HP;
    const __half2* eB = (const __half2*)g_ench + (long)b * T * HP + p;
    float ax[4], ay[4];
    #pragma unroll
    for (int j = 0; j < 4; ++j) { ax[j] = 0.f; ay[j] = 0.f; }
    const int tbeg = quar * TQ + sl * TSL, tend = tbeg + TSL;
    for (int t = tbeg; t < tend; t += 4) {
        #pragma unroll
        for (int j = 0; j < 4; ++j) {
            const float2 v = __half22float2(eB[(long)(t + j) * HP]);
            const float w = sW[t + j];
            ax[j] += w * v.x;
            ay[j] += w * v.y;
        }
    }
    sPx[sl][p] = (ax[0] + ax[1]) + (ax[2] + ax[3]);
    sPy[sl][p] = (ay[0] + ay[1]) + (ay[2] + ay[3]);
    __syncthreads();
    if (tid < H) {
        const int pp = tid >> 1;
        float acc = 0.f;
        if (tid & 1) {
            #pragma unroll
            for (int s = 0; s < NSL; ++s) acc += sPy[s][pp];
        } else {
            #pragma unroll
            for (int s = 0; s < NSL; ++s) acc += sPx[s][pp];
        }
        g_ctxpart[quar][b * H + tid] = acc * inv;
    }
}

// ============================================================
// Kernel 3.5: gate base GEMM v3 — software-pipelined weight staging.
// Unified k = 400 (ctx || q), 10 chunks of 40, next chunk's weights
// held in registers while current chunk computes. float4 compute.
// grid (8, 16), 800 threads: 100 gates x 8 batches.
// ============================================================
#define GCH 40
#define NGCH 10
#define WPAD 44    // padded row stride (words): stride-12 banks, conflict-free

__global__ void k_gates(const float* __restrict__ h0, const float* __restrict__ Wih,
                        const float* __restrict__ Whh, const float* __restrict__ bih,
                        const float* __restrict__ bhh) {
    __shared__ float sSrc[8][400];            // 12.8 KB: [batch][ctx(200) || q(200)]
    __shared__ __align__(16) float sWf[2][100 * WPAD];  // 35.2 KB
    const int tid  = threadIdx.x;
    const int gl   = tid % 100;
    const int bb   = tid / 100;
    const int gBase = blockIdx.x * 100;
    const int b0   = blockIdx.y * 8;
    const int g    = gBase + gl;

    for (int i = tid; i < 8 * 400; i += 800) {
        const int r = i / 400, k = i % 400;
        const int idx = (b0 + r) * H;
        sSrc[r][k] = (k < 200)
            ? (g_ctxpart[0][idx + k] + g_ctxpart[1][idx + k])
              + (g_ctxpart[2][idx + k] + g_ctxpart[3][idx + k])
            : h0[idx + (k - 200)];
    }

    // weight chunk loader: 5 words/thread, unified-k addressing
    auto ldw = [&](int cchunk, float* regs) {
        #pragma unroll
        for (int u = 0; u < 5; ++u) {
            const int idx = u * 800 + tid;          // 0..3999
            const int row = idx / GCH, col = idx - row * GCH;
            const int k = cchunk * GCH + col;
            const int gg = gBase + row;
            regs[u] = (k < 200) ? Wih[gg * (H + 1) + 1 + k]
                                : Whh[gg * H + (k - 200)];
        }
    };

    float regs[5], nregs[5];
    ldw(0, regs);
    float acc = bih[g] + bhh[g];
    const float4* src4 = (const float4*)&sSrc[bb][0];

    for (int cchunk = 0; cchunk < NGCH; ++cchunk) {
        const int st = cchunk & 1;
        #pragma unroll
        for (int u = 0; u < 5; ++u) {
            const int idx = u * 800 + tid;
            const int row = idx / GCH, col = idx - row * GCH;
            sWf[st][row * WPAD + col] = regs[u];
        }
        __syncthreads();
        if (cchunk + 1 < NGCH) ldw(cchunk + 1, nregs);   // overlaps compute below

        const float4* w4 = (const float4*)&sWf[st][gl * WPAD];
        const int kb = cchunk * (GCH / 4);
        float a0 = 0.f, a1 = 0.f, a2 = 0.f, a3 = 0.f;
        #pragma unroll
        for (int j = 0; j < GCH / 4; ++j) {
            const float4 w = w4[j];
            const float4 s = src4[kb + j];
            a0 += w.x * s.x; a1 += w.y * s.y; a2 += w.z * s.z; a3 += w.w * s.w;
        }
        acc += (a0 + a1) + (a2 + a3);
        #pragma unroll
        for (int u = 0; u < 5; ++u) regs[u] = nregs[u];
        __syncthreads();
    }
    g_gbase[(b0 + bb) * G4 + g] = acc;
}

// ============================================================
// Kernel 4: decoder (unchanged)
// ============================================================
__global__ void k_dec(const float* __restrict__ x, const float* __restrict__ c0in,
                      const float* __restrict__ Wih,
                      const float* __restrict__ W1, const float* __restrict__ b1,
                      const float* __restrict__ W2, const float* __restrict__ b2,
                      const float* __restrict__ W3, const float* __restrict__ b3,
                      float* __restrict__ out) {
    __shared__ float sGB[G4];
    __shared__ float sWx[G4];
    __shared__ float sR[H];
    __shared__ float sO1[100];
    __shared__ float sO2[52];
    __shared__ float sRed[64];
    __shared__ float sY;
    __shared__ float sW2[5000];
    __shared__ float sW3[52];
    __shared__ float sB1[100];
    __shared__ float sB2c[52];

    const int b = blockIdx.x, tid = threadIdx.x;
    const int lane = tid & 31;
    const unsigned m8  = 0xFFu   << (lane & 24);
    const unsigned m16 = 0xFFFFu << (lane & 16);

    for (int i = tid; i < 5000; i += G4) sW2[i] = W2[i];
    if (tid < 50)  sW3[tid] = W3[tid];
    if (tid < 100) sB1[tid] = b1[tid];
    if (tid < 50)  sB2c[tid] = b2[tid];
    sGB[tid] = g_gbase[b * G4 + tid];
    sWx[tid] = Wih[tid * (H + 1)];

    const int j8 = tid >> 3, q8 = tid & 7;
    float w1r[25];
    {
        const float* w1p = W1 + j8 * H + q8 * 25;
        #pragma unroll
        for (int k = 0; k < 25; ++k) w1r[k] = w1p[k];
    }
    const float cprev = (tid < H) ? c0in[b * H + tid] : 0.f;
    __syncthreads();

    float xt = x[b];
    const int j16 = tid >> 4, q16 = tid & 15;
    for (int s = 0; s < NSTEP; ++s) {
        if (tid < H) {
            const float gi = sGB[tid]         + xt * sWx[tid];
            const float gf = sGB[H + tid]     + xt * sWx[H + tid];
            const float gg = sGB[2 * H + tid] + xt * sWx[2 * H + tid];
            const float go = sGB[3 * H + tid] + xt * sWx[3 * H + tid];
            const float c  = sig_fast(gf) * cprev + sig_fast(gi) * tanh_fast(gg);
            const float h  = sig_fast(go) * tanh_fast(c);
            sR[tid] = fmaxf(h, 0.f);
        }
        __syncthreads();
        {
            const float* r = sR + q8 * 25;
            float v = 0.f;
            #pragma unroll
            for (int k = 0; k < 25; ++k) v += w1r[k] * r[k];
            v += __shfl_xor_sync(m8, v, 1);
            v += __shfl_xor_sync(m8, v, 2);
            v += __shfl_xor_sync(m8, v, 4);
            if (q8 == 0) sO1[j8] = fmaxf(v + sB1[j8], 0.f);
        }
        __syncthreads();
        {
            const float* w = sW2 + j16 * 100;
            float v = 0.f;
            #pragma unroll
            for (int kk = 0; kk < 7; ++kk) {
                const int k = q16 * 7 + kk;
                if (k < 100) v += w[k] * sO1[k];
            }
            v += __shfl_xor_sync(m16, v, 1);
            v += __shfl_xor_sync(m16, v, 2);
            v += __shfl_xor_sync(m16, v, 4);
            v += __shfl_xor_sync(m16, v, 8);
            if (q16 == 0) sO2[j16] = fmaxf(v + sB2c[j16], 0.f);
        }
        __syncthreads();
        if (tid < 64) sRed[tid] = (tid < 50) ? sW3[tid] * sO2[tid] : 0.f;
        __syncthreads();
        if (tid < 32) {
            float v = sRed[tid] + sRed[tid + 32];
            #pragma unroll
            for (int o = 16; o; o >>= 1) v += __shfl_xor_sync(0xffffffffu, v, o);
            if (tid == 0) { float y = v + b3[0]; out[b * NSTEP + s] = y; sY = y; }
        }
        __syncthreads();
        xt = sY;
    }
}

// ============================================================
extern "C" void kernel_launch(void* const* d_in, const int* in_sizes, int n_in,
                              void* d_out, int out_size) {
    const float* x   = (const float*)d_in[0];
    const float* h0  = (const float*)d_in[1];
    const float* c0  = (const float*)d_in[2];
    const float* enc = (const float*)d_in[3];
    const float* Wa  = (const float*)d_in[4];
    const float* ba  = (const float*)d_in[5];
    const float* Ua  = (const float*)d_in[6];
    const float* bua = (const float*)d_in[7];
    const float* Va  = (const float*)d_in[8];
    // d_in[9] = bva (softmax-shift-invariant, unused)
    const float* Wih = (const float*)d_in[10];
    const float* Whh = (const float*)d_in[11];
    const float* bih = (const float*)d_in[12];
    const float* bhh = (const float*)d_in[13];
    const float* W1  = (const float*)d_in[14];
    const float* b1  = (const float*)d_in[15];
    const float* W2  = (const float*)d_in[16];
    const float* b2  = (const float*)d_in[17];
    const float* W3  = (const float*)d_in[18];
    const float* b3  = (const float*)d_in[19];
    float* out = (float*)d_out;

    const long ncvt = N8E + N8U;
    k_cvt<<<(int)((ncvt + 255) / 256), 256>>>(enc, Ua);
    k_pre<<<B, 256>>>(h0, Wa, ba);
    k_scores_mma<<<dim3(T / TMR, B), 256>>>(bua, Va);
    k_ctx<<<dim3(B, 4), CTXTH>>>();
    k_gates<<<dim3(8, 16), 800>>>(h0, Wih, Whh, bih, bhh);
    k_dec<<<B, G4>>>(x, c0, Wih, W1, b1, W2, b2, W3, b3, out);
}